// round 10
// baseline (speedup 1.0000x reference)
#include <cuda_runtime.h>
#include <math.h>
#include <float.h>
#include <stdint.h>

#define BB 4
#define NSEQ 1024
#define DQ 256
#define HH 8
#define DH 32
#define NTOK (BB*NSEQ)          // 4096
#define QSCALE 0.17677669529663687f  // 32^-0.5

typedef unsigned int u32;

// ---------------- device scratch (allocation-free rule) ----------------
// Fragment-order tf32 operands:
// Qf[bh][it16][wm4][ks4][lane32][slot4]   (2048 words per (bh,it))
__device__ u32 Qf[32*16*4*4*32*4];
// Kf[bh][jt16][jb8][ks4][lane32][s2]      (2048 words per (bh,jt))
__device__ u32 Kf[32*16*8*4*32*2];
// Vf[bh][jt16][db4][ksj8][lane32][s2]     (2048 words per (bh,jt))
__device__ u32 Vf[32*16*4*8*32*2];
// Packed weights, fragment order: Wallf[eb128][ks32][lane32][s2], Wof[eb32][ks32][lane32][s2]
__device__ u32 Wallf[128*32*32*2];
__device__ u32 Wof[32*32*32*2];
__device__ float g_Sig[NTOK*DQ];   // [token][256]
__device__ float g_O[NTOK*DQ];     // [token][256]

__device__ __forceinline__ u32 f2tf(float x){
    u32 u; asm("cvt.rna.tf32.f32 %0, %1;" : "=r"(u) : "f"(x)); return u;
}
__device__ __forceinline__ void mma_tf32(float c[4],
    u32 a0, u32 a1, u32 a2, u32 a3, u32 b0, u32 b1)
{
    asm volatile(
        "mma.sync.aligned.m16n8k8.row.col.f32.tf32.tf32.f32 "
        "{%0,%1,%2,%3},{%4,%5,%6,%7},{%8,%9},{%0,%1,%2,%3};"
        : "+f"(c[0]), "+f"(c[1]), "+f"(c[2]), "+f"(c[3])
        : "r"(a0), "r"(a1), "r"(a2), "r"(a3), "r"(b0), "r"(b1));
}

// ============================================================
// Kernel 0: repack weights into fragment order (tf32 bits)
// ============================================================
__global__ __launch_bounds__(256) void repack_kernel(
    const float* __restrict__ Wq, const float* __restrict__ Wkv,
    const float* __restrict__ Wg, const float* __restrict__ Wo)
{
    int i = blockIdx.x * 256 + threadIdx.x;
    if (i < 128*32*32*2) {
        int w = i;
        int s = w & 1, lane = (w >> 1) & 31, ks = (w >> 6) & 31, eb = w >> 11;
        int e = eb*8 + (lane >> 2);
        int c = ks*8 + s*4 + (lane & 3);
        float v;
        if (e < 256)      v = Wq[e*256 + c];
        else if (e < 768) v = Wkv[(e-256)*256 + c];
        else              v = Wg[(e-768)*256 + c];
        Wallf[w] = f2tf(v);
    } else {
        int w = i - 128*32*32*2;
        if (w < 32*32*32*2) {
            int s = w & 1, lane = (w >> 1) & 31, ks = (w >> 6) & 31, eb = w >> 11;
            int e = eb*8 + (lane >> 2);
            int c = ks*8 + s*4 + (lane & 3);
            Wof[w] = f2tf(Wo[e*256 + c]);
        }
    }
}

// ============================================================
// Kernel 1: projections. C[4096,1024] = x[4096,256] @ Wall^T
// Epilogue: fragment scatter into SMEM, then coalesced STG.128.
// ============================================================
__global__ __launch_bounds__(256) void proj_kernel(
    const float* __restrict__ x, const float* __restrict__ bg)
{
    __shared__ u32 Af[4*4*32*4];   // 2KB
    __shared__ u32 Bf[8*4*32*2];   // 1KB
    __shared__ u32 Sf[4096];       // 16KB output staging (2 heads x 2048 words)

    const int tid = threadIdx.x;
    const int m0 = blockIdx.y * 64;
    const int e0 = blockIdx.x * 64;
    const int eb0 = e0 >> 3;

    const int warp = tid >> 5, lane = tid & 31;
    const int wm = warp & 3, wn = warp >> 2;
    const int g = lane >> 2, t4 = lane & 3;

    float acc[4][4];
    #pragma unroll
    for (int nt = 0; nt < 4; nt++)
        #pragma unroll
        for (int i = 0; i < 4; i++) acc[nt][i] = 0.f;

    for (int k0 = 0; k0 < 256; k0 += 32) {
        const int kb0 = k0 >> 3;
        // ---- load A (x tile 64x32) into fragment smem ----
        #pragma unroll
        for (int u = 0; u < 2; u++) {
            int it = tid + 256*u;
            int r = it >> 3, c4 = (it & 7) << 2;
            float4 xv = *(const float4*)&x[(size_t)(m0 + r)*256 + k0 + c4];
            int wmr = r >> 4, gr = r & 15, ks = c4 >> 3, lo4 = c4 & 7;
            int slot = (gr < 8) ? (lo4 ? 2 : 0) : (lo4 ? 3 : 1);
            int lane0 = (gr & 7) * 4;
            u32* dst = &Af[((wmr*4 + ks)*32 + lane0)*4 + slot];
            dst[0]  = f2tf(xv.x);
            dst[4]  = f2tf(xv.y);
            dst[8]  = f2tf(xv.z);
            dst[12] = f2tf(xv.w);
        }
        // ---- load B (Wallf chunk) linear copy ----
        #pragma unroll
        for (int u = 0; u < 2; u++) {
            int i4 = tid + 256*u;              // 512 uint4 total
            int chunk = i4 >> 4, w16 = i4 & 15;
            int ebp = chunk >> 2, ksl = chunk & 3;
            const u32* src = &Wallf[(((eb0 + ebp)*32 + kb0 + ksl)*32)*2 + w16*4];
            *(uint4*)&Bf[i4*4] = *(const uint4*)src;
        }
        __syncthreads();
        #pragma unroll
        for (int ks = 0; ks < 4; ks++) {
            uint4 av = *(const uint4*)&Af[((wm*4 + ks)*32 + lane)*4];
            #pragma unroll
            for (int nt = 0; nt < 4; nt++) {
                int nb = wn*4 + nt;
                uint2 bv = *(const uint2*)&Bf[((nb*4 + ks)*32 + lane)*2];
                mma_tf32(acc[nt], av.x, av.y, av.z, av.w, bv.x, bv.y);
            }
        }
        __syncthreads();
    }

    // ---- epilogue ----
    const int b  = m0 >> 10;             // batch (tiles never cross batch)
    const int tt = (m0 & 1023) >> 6;     // it or jt

    if (e0 < 768) {
        // scatter fragments into smem image of the 2 contiguous head regions
        #pragma unroll
        for (int nt = 0; nt < 4; nt++) {
            #pragma unroll
            for (int i = 0; i < 4; i++) {
                int rl = wm*16 + g + ((i >= 2) ? 8 : 0);     // local row 0..63
                int el = wn*32 + nt*8 + t4*2 + (i & 1);      // local e   0..63
                float v = acc[nt][i];
                int d = el & 31;
                int idx; u32 w;
                if (e0 < 256) {
                    int wmq = rl >> 4, gq = rl & 15;
                    int dd = d & 7, ksq = d >> 3;
                    int lq = (gq & 7)*4 + (dd & 3);
                    int slot = (gq < 8) ? (dd < 4 ? 0 : 2) : (dd < 4 ? 1 : 3);
                    idx = ((el >> 5) & 1)*2048 + ((wmq*4 + ksq)*32 + lq)*4 + slot;
                    w = f2tf(v * QSCALE);
                } else if (e0 < 512) {
                    int jb = rl >> 3, gk = rl & 7;
                    int dd = d & 7, ksq = d >> 3;
                    int lk = gk*4 + (dd & 3), s = (dd < 4) ? 0 : 1;
                    idx = ((el >> 5) & 1)*2048 + ((jb*4 + ksq)*32 + lk)*2 + s;
                    w = f2tf(v);
                } else {
                    int ksj = rl >> 3, jj = rl & 7;
                    int s = (jj < 4) ? 0 : 1;
                    int lv = (d & 7)*4 + (jj & 3);
                    int db = d >> 3;
                    idx = ((el >> 5) & 1)*2048 + ((db*8 + ksj)*32 + lv)*2 + s;
                    w = f2tf(v);
                }
                Sf[idx] = w;
            }
        }
        __syncthreads();

        // coalesced copy: 2 heads x 2048 contiguous words each
        u32* dstbase; int h0;
        if (e0 < 256)      { h0 = e0 >> 5;         dstbase = Qf; }
        else if (e0 < 512) { h0 = (e0 - 256) >> 5; dstbase = Kf; }
        else               { h0 = (e0 - 512) >> 5; dstbase = Vf; }
        #pragma unroll
        for (int hh = 0; hh < 2; hh++) {
            u32* dst = dstbase + ((size_t)((b*8 + h0 + hh)*16 + tt))*2048;
            const u32* src = Sf + hh*2048;
            *(uint4*)(dst + tid*4)        = *(const uint4*)(src + tid*4);
            *(uint4*)(dst + 1024 + tid*4) = *(const uint4*)(src + 1024 + tid*4);
        }
    } else {
        // gate mode: direct write (reasonably coalesced), as before
        #pragma unroll
        for (int nt = 0; nt < 4; nt++) {
            #pragma unroll
            for (int i = 0; i < 4; i++) {
                int r = m0 + wm*16 + g + ((i >= 2) ? 8 : 0);
                int e = e0 + wn*32 + nt*8 + t4*2 + (i & 1);
                int eg = e - 768;
                float z = acc[nt][i] + bg[eg];
                g_Sig[(size_t)r*256 + eg] = 1.f / (1.f + __expf(-z));
            }
        }
    }
}

// ============================================================
// Kernel 2: flash attention. grid (16 i-tiles, 32 bh), 256 thr.
// ============================================================
__global__ __launch_bounds__(256) void attn_kernel(
    const float* __restrict__ bias, const float* __restrict__ mask)
{
    __shared__ u32 Ks[2048];          // 8KB: [jb8][ks4][lane32][s2]
    __shared__ u32 Vs[2048];          // 8KB: [db4][ksj8][lane32][s2]
    __shared__ float Ssm[64][68];     // S then P(tf32 bits), pad 68
    __shared__ float s_alpha[64];
    __shared__ float s_l[64];
    __shared__ float s_cmask[64];

    const int tid = threadIdx.x, warp = tid >> 5, lane = tid & 31;
    const int wm = warp & 3, wn = warp >> 2;
    const int g = lane >> 2, t4 = lane & 3;
    const int bh = blockIdx.y, b = bh >> 3, h = bh & 7;
    const int it = blockIdx.x, i0 = it * 64;

    // ---- Q fragments (register-resident, tf32 bits) ----
    u32 qa[4][4];
    {
        const u32* qp = Qf + (((size_t)(bh*16 + it)*4 + wm)*4)*32*4;
        #pragma unroll
        for (int ks = 0; ks < 4; ks++) {
            uint4 t = *(const uint4*)(qp + (size_t)(ks*32 + lane)*4);
            qa[ks][0] = t.x; qa[ks][1] = t.y; qa[ks][2] = t.z; qa[ks][3] = t.w;
        }
    }

    // softmax mapping: thread = (row srow, quad q4) owns cols 16*q4..+15
    const int srow = tid >> 2, q4 = tid & 3, scol = q4 * 16;
    const bool rok = mask[b*1024 + i0 + srow] > 0.f;
    float m_run = -FLT_MAX, l_run = 0.f;

    float oacc[2][4];
    #pragma unroll
    for (int nt = 0; nt < 2; nt++)
        #pragma unroll
        for (int i = 0; i < 4; i++) oacc[nt][i] = 0.f;

    const float* bias_row = bias + ((size_t)(bh*1024 + i0 + srow))*1024 + scol;
    const u32* kgb = Kf + (size_t)(bh*16)*2048;
    const u32* vgb = Vf + (size_t)(bh*16)*2048;

    // prefetch tile 0 K/V + cmask into registers
    uint4 kr0, kr1, vr0, vr1; float4 cmv = make_float4(0,0,0,0);
    {
        const u32* kp = kgb; const u32* vp = vgb;
        kr0 = *(const uint4*)(kp + tid*4);
        kr1 = *(const uint4*)(kp + 1024 + tid*4);
        vr0 = *(const uint4*)(vp + tid*4);
        vr1 = *(const uint4*)(vp + 1024 + tid*4);
        if (tid < 16) cmv = *(const float4*)&mask[b*1024 + tid*4];
    }

    for (int jt = 0; jt < 16; jt++) {
        // stage K/V/cmask (prev PV finished: sync at loop end)
        *(uint4*)&Ks[tid*4] = kr0;  *(uint4*)&Ks[1024 + tid*4] = kr1;
        *(uint4*)&Vs[tid*4] = vr0;  *(uint4*)&Vs[1024 + tid*4] = vr1;
        if (tid < 16) *(float4*)&s_cmask[tid*4] = cmv;

        // bias prefetch for THIS tile (consumed in softmax)
        float bf[16];
        {
            const float* bp = bias_row + jt*64;
            #pragma unroll
            for (int u = 0; u < 4; u++) {
                float4 t = *(const float4*)(bp + u*4);
                bf[4*u+0] = t.x; bf[4*u+1] = t.y; bf[4*u+2] = t.z; bf[4*u+3] = t.w;
            }
        }
        __syncthreads();   // (a) K/V/cmask visible

        // prefetch next tile K/V into registers (overlaps compute)
        if (jt < 15) {
            const u32* kp = kgb + (size_t)(jt + 1)*2048;
            const u32* vp = vgb + (size_t)(jt + 1)*2048;
            kr0 = *(const uint4*)(kp + tid*4);
            kr1 = *(const uint4*)(kp + 1024 + tid*4);
            vr0 = *(const uint4*)(vp + tid*4);
            vr1 = *(const uint4*)(vp + 1024 + tid*4);
            if (tid < 16) cmv = *(const float4*)&mask[b*1024 + (jt+1)*64 + tid*4];
        }

        // ---- S = Q K^T ----
        float sc[4][4];
        #pragma unroll
        for (int nt = 0; nt < 4; nt++)
            #pragma unroll
            for (int i = 0; i < 4; i++) sc[nt][i] = 0.f;
        #pragma unroll
        for (int ks = 0; ks < 4; ks++) {
            #pragma unroll
            for (int nt = 0; nt < 4; nt++) {
                int jb = wn*4 + nt;
                uint2 bv = *(const uint2*)&Ks[((jb*4 + ks)*32 + lane)*2];
                mma_tf32(sc[nt], qa[ks][0], qa[ks][1], qa[ks][2], qa[ks][3], bv.x, bv.y);
            }
        }
        // S fragments -> Ssm (fp32, row-major)
        #pragma unroll
        for (int nt = 0; nt < 4; nt++) {
            int c0 = wn*32 + nt*8 + t4*2;
            *(float2*)&Ssm[wm*16 + g][c0]     = make_float2(sc[nt][0], sc[nt][1]);
            *(float2*)&Ssm[wm*16 + 8 + g][c0] = make_float2(sc[nt][2], sc[nt][3]);
        }
        __syncthreads();   // (b)

        // ---- online softmax (in-place: S fp32 -> P tf32 bits) ----
        {
            float sv[16]; float mx = -FLT_MAX;
            #pragma unroll
            for (int u4 = 0; u4 < 4; u4++) {
                float4 s4 = *(const float4*)&Ssm[srow][scol + u4*4];
                float ss[4] = {s4.x, s4.y, s4.z, s4.w};
                #pragma unroll
                for (int v = 0; v < 4; v++) {
                    int u = u4*4 + v;
                    float cm = s_cmask[scol + u];
                    float s = (rok && cm > 0.f) ? (ss[v] + bf[u]) : -FLT_MAX;
                    sv[u] = s; mx = fmaxf(mx, s);
                }
            }
            mx = fmaxf(mx, __shfl_xor_sync(0xffffffffu, mx, 1));
            mx = fmaxf(mx, __shfl_xor_sync(0xffffffffu, mx, 2));
            float m_new = fmaxf(m_run, mx);
            float sum = 0.f;
            #pragma unroll
            for (int u4 = 0; u4 < 4; u4++) {
                float4 pw;
                float p0 = __expf(sv[u4*4+0] - m_new);
                float p1 = __expf(sv[u4*4+1] - m_new);
                float p2 = __expf(sv[u4*4+2] - m_new);
                float p3 = __expf(sv[u4*4+3] - m_new);
                sum += (p0 + p1) + (p2 + p3);
                pw.x = __uint_as_float(f2tf(p0));
                pw.y = __uint_as_float(f2tf(p1));
                pw.z = __uint_as_float(f2tf(p2));
                pw.w = __uint_as_float(f2tf(p3));
                *(float4*)&Ssm[srow][scol + u4*4] = pw;
            }
            sum += __shfl_xor_sync(0xffffffffu, sum, 1);
            sum += __shfl_xor_sync(0xffffffffu, sum, 2);
            float alpha = __expf(m_run - m_new);
            l_run = l_run * alpha + sum;
            m_run = m_new;
            if (q4 == 0) s_alpha[srow] = alpha;
        }
        __syncthreads();   // (c)

        // ---- O = O*alpha + P V ----
        {
            float a_lo = s_alpha[wm*16 + g];
            float a_hi = s_alpha[wm*16 + 8 + g];
            #pragma unroll
            for (int nt = 0; nt < 2; nt++) {
                oacc[nt][0] *= a_lo; oacc[nt][1] *= a_lo;
                oacc[nt][2] *= a_hi; oacc[nt][3] *= a_hi;
            }
            #pragma unroll
            for (int ksj = 0; ksj < 8; ksj++) {
                u32 p0 = __float_as_uint(Ssm[wm*16 + g    ][ksj*8 + t4    ]);
                u32 p1 = __float_as_uint(Ssm[wm*16 + 8 + g][ksj*8 + t4    ]);
                u32 p2 = __float_as_uint(Ssm[wm*16 + g    ][ksj*8 + 4 + t4]);
                u32 p3 = __float_as_uint(Ssm[wm*16 + 8 + g][ksj*8 + 4 + t4]);
                #pragma unroll
                for (int ntd = 0; ntd < 2; ntd++) {
                    int db = wn*2 + ntd;
                    uint2 vv = *(const uint2*)&Vs[((db*8 + ksj)*32 + lane)*2];
                    mma_tf32(oacc[ntd], p0, p1, p2, p3, vv.x, vv.y);
                }
            }
        }
        __syncthreads();   // (d) protect Ks/Vs/Ssm for next tile
    }

    if (q4 == 0) s_l[srow] = l_run;
    __syncthreads();
    {
        float il_lo = 1.f / s_l[wm*16 + g];
        float il_hi = 1.f / s_l[wm*16 + 8 + g];
        #pragma unroll
        for (int nt = 0; nt < 2; nt++) {
            #pragma unroll
            for (int i = 0; i < 4; i++) {
                int r = i0 + wm*16 + g + ((i >= 2) ? 8 : 0);
                int d = wn*16 + nt*8 + t4*2 + (i & 1);
                float il = (i >= 2) ? il_hi : il_lo;
                g_O[(size_t)(b*1024 + r)*256 + h*32 + d] = oacc[nt][i] * il;
            }
        }
    }
}

// ============================================================
// Kernel 3: out = (O .* Sig) @ Wo^T + bo
// 32-row tiles, grid (4,128) for 2x occupancy.
// ============================================================
__global__ __launch_bounds__(256) void out_kernel(
    const float* __restrict__ bo, float* __restrict__ out)
{
    __shared__ u32 Af[2*4*32*4];   // 1024 words: [wm2][ks4][lane32][slot4]
    __shared__ u32 Bf[8*4*32*2];   // 2048 words

    const int tid = threadIdx.x;
    const int m0 = blockIdx.y * 32;
    const int e0 = blockIdx.x * 64;
    const int eb0 = e0 >> 3;

    const int warp = tid >> 5, lane = tid & 31;
    const int wm = warp & 1, wn = warp >> 1;   // wm 0..1, wn 0..3
    const int g = lane >> 2, t4 = lane & 3;

    float acc[2][4];
    #pragma unroll
    for (int nt = 0; nt < 2; nt++)
        #pragma unroll
        for (int i = 0; i < 4; i++) acc[nt][i] = 0.f;

    for (int k0 = 0; k0 < 256; k0 += 32) {
        const int kb0 = k0 >> 3;
        // ---- A: (O.*Sig) 32x32 tile -> fragment smem (1 float4/thread) ----
        {
            int r = tid >> 3, c4 = (tid & 7) << 2;     // r 0..31
            size_t ia = (size_t)(m0 + r)*256 + k0 + c4;
            float4 o4 = *(const float4*)&g_O[ia];
            float4 s4 = *(const float4*)&g_Sig[ia];
            int wmr = r >> 4, gr = r & 15, ks = c4 >> 3, lo4 = c4 & 7;
            int slot = (gr < 8) ? (lo4 ? 2 : 0) : (lo4 ? 3 : 1);
            int lane0 = (gr & 7) * 4;
            u32* dst = &Af[((wmr*4 + ks)*32 + lane0)*4 + slot];
            dst[0]  = f2tf(o4.x * s4.x);
            dst[4]  = f2tf(o4.y * s4.y);
            dst[8]  = f2tf(o4.z * s4.z);
            dst[12] = f2tf(o4.w * s4.w);
        }
        // ---- B: Wof chunk, linear copy (2 uint4/thread) ----
        #pragma unroll
        for (int u = 0; u < 2; u++) {
            int i4 = tid + 256*u;
            int chunk = i4 >> 4, w16 = i4 & 15;
            int ebp = chunk >> 2, ksl = chunk & 3;
            const u32* src = &Wof[(((eb0 + ebp)*32 + kb0 + ksl)*32)*2 + w16*4];
            *(uint4*)&Bf[i4*4] = *(const uint4*)src;
        }
        __syncthreads();
        #pragma unroll
        for (int ks = 0; ks < 4; ks++) {
            uint4 av = *(const uint4*)&Af[((wm*4 + ks)*32 + lane)*4];
            #pragma unroll
            for (int nt = 0; nt < 2; nt++) {
                int nb = wn*2 + nt;
                uint2 bv = *(const uint2*)&Bf[((nb*4 + ks)*32 + lane)*2];
                mma_tf32(acc[nt], av.x, av.y, av.z, av.w, bv.x, bv.y);
            }
        }
        __syncthreads();
    }

    #pragma unroll
    for (int nt = 0; nt < 2; nt++) {
        #pragma unroll
        for (int i = 0; i < 4; i++) {
            int r = m0 + wm*16 + g + ((i >= 2) ? 8 : 0);
            int e = e0 + wn*16 + nt*8 + t4*2 + (i & 1);
            out[(size_t)r*256 + e] = acc[nt][i] + bo[e];
        }
    }
}

extern "C" void kernel_launch(void* const* d_in, const int* in_sizes, int n_in,
                              void* d_out, int out_size)
{
    const float* x    = (const float*)d_in[0];
    const float* mask = (const float*)d_in[1];
    const float* bias = (const float*)d_in[2];
    const float* Wq   = (const float*)d_in[3];
    const float* Wkv  = (const float*)d_in[4];
    const float* Wo   = (const float*)d_in[5];
    const float* bo   = (const float*)d_in[6];
    const float* Wg   = (const float*)d_in[7];
    const float* bg   = (const float*)d_in[8];
    float* out = (float*)d_out;

    repack_kernel<<<1280, 256>>>(Wq, Wkv, Wg, Wo);
    proj_kernel<<<dim3(16, 64), 256>>>(x, bg);
    attn_kernel<<<dim3(16, 32), 256>>>(bias, mask);
    out_kernel<<<dim3(4, 128), 256>>>(bo, out);
}